// round 16
// baseline (speedup 1.0000x reference)
#include <cuda_runtime.h>
#include <math_constants.h>
#include <cstdint>

// FLoss: weighted BCE, weights = W / (dist_to_argmax_centroid + 1)
// input  d_in[0]: [B,1,T,W,W] f32  (same linear layout as [B,T,W,W])
// target d_in[1]: [B,T,W,W]   f32
// out: scalar f32 = -mean(w * (t*clip(log p,-100) + (1-t)*clip(log1p(-p),-100)))
//
// Single launch, two CTA roles, producer/consumer overlap:
//   CTAs [0, nframes)        : per-frame max+centroid (branchless chains),
//                              publish g_c[f] then release g_flag[f].
//   CTAs [nframes, +LOSS_CTAS): weighted BCE, frame-aligned grid-stride;
//                              spin-acquire g_flag[f] per iteration.
// Stats CTAs occupy low bids -> all in wave 1 (launch_bounds(256,4) ensures
// >=4 CTAs/SM = 592 wave-1 CTAs > 256) -> no deadlock. Flags stay set across
// graph replays (benign: replays recompute identical centroids).

#define FRAME_ELEMS4 16384                 // 65536 elems / 4
#define MAX_FRAMES 4096

#define LOSS_CTAS   2368                   // stride 2368*256 = 37*16384 float4
#define FRAME_STEP  37

__device__ float2   g_c[MAX_FRAMES];
__device__ int      g_flag[MAX_FRAMES];    // 0 at load; set to 1 when frame ready
__device__ double   g_acc;
__device__ unsigned g_done;

#define LOG2_CLAMP (-144.26950408889634f)  // -100 / ln(2)
#define LN2F        (0.6931471805599453f)

__global__ __launch_bounds__(256, 4) void floss_overlap_kernel(
    const float* __restrict__ inp,
    const float* __restrict__ tgt,
    float* __restrict__ out,
    double inv_n, int nframes, int total4)
{
    const int tid = threadIdx.x;

    // =======================  ROLE 1: stats  ==============================
    if (blockIdx.x < (unsigned)nframes) {
        const int f = blockIdx.x;
        const float4* base = reinterpret_cast<const float4*>(tgt) + (size_t)f * FRAME_ELEMS4;

        float lm[4], cn[4], sx[4], sy[4];
        #pragma unroll
        for (int c = 0; c < 4; c++) { lm[c] = -CUDART_INF_F; cn[c] = 0.f; sx[c] = 0.f; sy[c] = 0.f; }

        #pragma unroll 8
        for (int k = 0; k < 64; k++) {
            const int e4 = tid + k * 256;
            const float4 v = __ldg(base + e4);
            const float row  = (float)(e4 >> 6);
            const float col0 = (float)((e4 & 63) * 4);
            const float vals[4] = {v.x, v.y, v.z, v.w};
            #pragma unroll
            for (int c = 0; c < 4; c++) {
                const float val = vals[c];
                const float col = col0 + (float)c;
                const bool gt = (val >  lm[c]);
                const bool eq = (val == lm[c]);
                cn[c] = gt ? 1.f : (cn[c] + (eq ? 1.f : 0.f));
                sx[c] = gt ? row : (sx[c] + (eq ? row : 0.f));
                sy[c] = gt ? col : (sy[c] + (eq ? col : 0.f));
                lm[c] = fmaxf(lm[c], val);
            }
        }

        float lmax = lm[0], cnt = cn[0], tsx = sx[0], tsy = sy[0];
        #pragma unroll
        for (int c = 1; c < 4; c++) {
            if (lm[c] > lmax)       { lmax = lm[c]; cnt = cn[c]; tsx = sx[c]; tsy = sy[c]; }
            else if (lm[c] == lmax) { cnt += cn[c]; tsx += sx[c]; tsy += sy[c]; }
        }

        __shared__ float s_wmax[8];
        __shared__ float s_gmax, s_sx, s_sy, s_cnt;

        float wm = lmax;
        #pragma unroll
        for (int o = 16; o; o >>= 1) wm = fmaxf(wm, __shfl_xor_sync(0xffffffffu, wm, o));
        if ((tid & 31) == 0) s_wmax[tid >> 5] = wm;
        if (tid == 0) { s_sx = 0.f; s_sy = 0.f; s_cnt = 0.f; }
        __syncthreads();
        if (tid < 32) {
            float m = (tid < 8) ? s_wmax[tid] : -CUDART_INF_F;
            #pragma unroll
            for (int o = 4; o; o >>= 1) m = fmaxf(m, __shfl_xor_sync(0xffffffffu, m, o));
            if (tid == 0) s_gmax = m;
        }
        __syncthreads();

        if (lmax == s_gmax) {              // rare
            atomicAdd(&s_cnt, cnt);
            atomicAdd(&s_sx,  tsx);
            atomicAdd(&s_sy,  tsy);
        }
        __syncthreads();

        if (tid == 0) {
            g_c[f] = make_float2(s_sx / s_cnt, s_sy / s_cnt);
            __threadfence();                         // release
            atomicExch(&g_flag[f], 1);
        }
        return;
    }

    // =======================  ROLE 2: loss  ===============================
    __shared__ double s_acc;
    if (tid == 0) s_acc = 0.0;
    __syncthreads();

    const float4* P = reinterpret_cast<const float4*>(inp);
    const float4* T = reinterpret_cast<const float4*>(tgt);

    const int li = blockIdx.x - nframes;
    const int i0 = li * 256 + tid;

    // loop-invariant geometry (stride is a multiple of 16384 float4)
    const float rowf = (float)((i0 >> 6) & 255);
    const float j0   = (float)((i0 & 63) * 4);
    int f = i0 >> 14;

    const int stride = LOSS_CTAS * 256;

    float lsum0 = 0.f, lsum1 = 0.f;
    for (int i = i0; i < total4; i += stride, f += FRAME_STEP) {
        // acquire: wait until frame f's centroid is published
        {
            volatile const int* fl = &g_flag[f];
            while (*fl == 0) __nanosleep(64);
            __threadfence();                 // acquire ordering for g_c[f]
        }
        const float2 cc = __ldg(&g_c[f]);

        const float4 p4 = __ldg(P + i);
        const float4 t4 = __ldg(T + i);

        const float di  = rowf - cc.x;
        const float di2 = di * di;
        const float jb  = j0 - cc.y;         // dj for lane c = jb + c

        #pragma unroll
        for (int c = 0; c < 4; c++) {
            const float p = (c == 0) ? p4.x : (c == 1) ? p4.y : (c == 2) ? p4.z : p4.w;
            const float t = (c == 0) ? t4.x : (c == 1) ? t4.y : (c == 2) ? t4.z : t4.w;

            const float dj = jb + (float)c;
            const float s  = fmaf(dj, dj, di2);
            float dist, wrcp;
            asm("sqrt.approx.f32 %0, %1;" : "=f"(dist) : "f"(s));    // sqrt.approx(0)=0
            asm("rcp.approx.f32 %0, %1;"  : "=f"(wrcp) : "f"(dist + 1.0f));

            float lp2, lq2;
            asm("lg2.approx.f32 %0, %1;" : "=f"(lp2) : "f"(p));
            asm("lg2.approx.f32 %0, %1;" : "=f"(lq2) : "f"(1.0f - p));
            lp2 = fmaxf(lp2, LOG2_CLAMP);
            lq2 = fmaxf(lq2, LOG2_CLAMP);
            const float term = fmaf(t, lp2 - lq2, lq2);   // log2 domain
            if (c & 1) lsum1 = fmaf(256.0f * wrcp, term, lsum1);
            else       lsum0 = fmaf(256.0f * wrcp, term, lsum0);
        }
    }
    float lsum = (lsum0 + lsum1) * LN2F;

    #pragma unroll
    for (int o = 16; o; o >>= 1) lsum += __shfl_xor_sync(0xffffffffu, lsum, o);
    if ((tid & 31) == 0) atomicAdd(&s_acc, (double)lsum);
    __syncthreads();

    if (tid == 0) {
        atomicAdd(&g_acc, s_acc);
        __threadfence();
        const unsigned t = atomicAdd(&g_done, 1u);
        if (t == LOSS_CTAS - 1) {                 // last loss CTA of this replay
            const double total = atomicAdd(&g_acc, 0.0);
            out[0] = (float)(-total * inv_n);
            g_acc = 0.0;                          // reset for next graph replay
            __threadfence();
            atomicExch(&g_done, 0u);
        }
    }
}

extern "C" void kernel_launch(void* const* d_in, const int* in_sizes, int n_in,
                              void* d_out, int out_size)
{
    const float* inp = (const float*)d_in[0];
    const float* tgt = (const float*)d_in[1];
    float* out = (float*)d_out;

    const int n       = in_sizes[1];       // B*T*W*W
    const int nframes = n >> 16;
    const int total4  = n >> 2;

    floss_overlap_kernel<<<nframes + LOSS_CTAS, 256>>>(inp, tgt, out,
                                                       1.0 / (double)n, nframes, total4);
}

// round 17
// speedup vs baseline: 1.5952x; 1.5952x over previous
#include <cuda_runtime.h>
#include <math_constants.h>
#include <cstdint>

// FLoss: weighted BCE, weights = W / (dist_to_argmax_centroid + 1)
// input  d_in[0]: [B,1,T,W,W] f32  (same linear layout as [B,T,W,W])
// target d_in[1]: [B,T,W,W]   f32
// out: scalar f32 = -mean(w * (t*clip(log p,-100) + (1-t)*clip(log1p(-p),-100)))
//
// Two-kernel split (the only structure that has worked):
//   K1: per-frame max+centroid, branchless chains, 1024thr/CTA (DRAM roofline)
//   K2: weighted BCE with 256-bit (v8) loads, frame-aligned stride, hoisted
//       geometry. 8 elems per thread-iter, half the LDG/address issue slots.

#define FRAME_ELEMS4 16384                 // 65536 elems / 4
#define MAX_FRAMES 4096

__device__ float2   g_c[MAX_FRAMES];       // per-frame centroid (cx, cy)
__device__ double   g_acc;
__device__ unsigned g_done;

#define LOG2_CLAMP (-144.26950408889634f)  // -100 / ln(2)
#define LN2F        (0.6931471805599453f)

// Loss grid: stride = LOSS_GRID*256 threads * 8 elems = 37 * 65536 elems
// -> per-thread row/col loop-invariant, frame index advances by 37.
#define LOSS_GRID   1184
#define FRAME_STEP  37

struct f8 { float v[8]; };

__device__ __forceinline__ f8 ldg256(const float* p) {
    f8 r;
    asm volatile("ld.global.nc.v8.b32 {%0,%1,%2,%3,%4,%5,%6,%7}, [%8];"
                 : "=f"(r.v[0]), "=f"(r.v[1]), "=f"(r.v[2]), "=f"(r.v[3]),
                   "=f"(r.v[4]), "=f"(r.v[5]), "=f"(r.v[6]), "=f"(r.v[7])
                 : "l"(p));
    return r;
}

// ---------------------------------------------------------------------------
// Kernel 1: per-frame max + centroid, single pass, branchless 4-chain.
// One CTA (1024 threads) per frame. Measured ~8.8us (~7.6 TB/s, roofline).
// Exact tie semantics (target == max), identical to reference.
// ---------------------------------------------------------------------------
__global__ __launch_bounds__(1024) void frame_stats_kernel(const float* __restrict__ tgt)
{
    const int f   = blockIdx.x;
    const int tid = threadIdx.x;
    const float4* base = reinterpret_cast<const float4*>(tgt) + (size_t)f * FRAME_ELEMS4;

    float lm[4], cn[4], sx[4], sy[4];
    #pragma unroll
    for (int c = 0; c < 4; c++) { lm[c] = -CUDART_INF_F; cn[c] = 0.f; sx[c] = 0.f; sy[c] = 0.f; }

    #pragma unroll
    for (int k = 0; k < 16; k++) {
        const int e4 = tid + k * 1024;
        const float4 v = __ldg(base + e4);
        const int e = e4 * 4;
        const float row  = (float)(e >> 8);
        const float col0 = (float)(e & 255);
        const float vals[4] = {v.x, v.y, v.z, v.w};
        #pragma unroll
        for (int c = 0; c < 4; c++) {
            const float val = vals[c];
            const float col = col0 + (float)c;
            const bool gt = (val >  lm[c]);
            const bool eq = (val == lm[c]);
            cn[c] = gt ? 1.f : (cn[c] + (eq ? 1.f : 0.f));
            sx[c] = gt ? row : (sx[c] + (eq ? row : 0.f));
            sy[c] = gt ? col : (sy[c] + (eq ? col : 0.f));
            lm[c] = fmaxf(lm[c], val);
        }
    }

    float lmax = lm[0], cnt = cn[0], tsx = sx[0], tsy = sy[0];
    #pragma unroll
    for (int c = 1; c < 4; c++) {
        if (lm[c] > lmax)       { lmax = lm[c]; cnt = cn[c]; tsx = sx[c]; tsy = sy[c]; }
        else if (lm[c] == lmax) { cnt += cn[c]; tsx += sx[c]; tsy += sy[c]; }
    }

    __shared__ float s_wmax[32];
    __shared__ float s_gmax, s_sx, s_sy, s_cnt;

    float wm = lmax;
    #pragma unroll
    for (int o = 16; o; o >>= 1) wm = fmaxf(wm, __shfl_xor_sync(0xffffffffu, wm, o));
    if ((tid & 31) == 0) s_wmax[tid >> 5] = wm;
    if (tid == 0) { s_sx = 0.f; s_sy = 0.f; s_cnt = 0.f; }
    __syncthreads();
    if (tid < 32) {
        float m = s_wmax[tid];
        #pragma unroll
        for (int o = 16; o; o >>= 1) m = fmaxf(m, __shfl_xor_sync(0xffffffffu, m, o));
        if (tid == 0) s_gmax = m;
    }
    __syncthreads();

    if (lmax == s_gmax) {
        atomicAdd(&s_cnt, cnt);
        atomicAdd(&s_sx,  tsx);
        atomicAdd(&s_sy,  tsy);
    }
    __syncthreads();

    if (tid == 0) {
        g_c[f] = make_float2(s_sx / s_cnt, s_sy / s_cnt);
        if (f == 0) { g_acc = 0.0; g_done = 0u; }   // per-replay reset (before loss)
    }
}

// ---------------------------------------------------------------------------
// Kernel 2: weighted BCE with 256-bit loads. Frame-aligned grid-stride,
// loop-invariant geometry. Two accumulators. Last CTA finalizes.
// ---------------------------------------------------------------------------
__global__ __launch_bounds__(256, 5) void loss_kernel(const float* __restrict__ inp,
                                                      const float* __restrict__ tgt,
                                                      int total8,
                                                      float* __restrict__ out,
                                                      double inv_n)
{
    __shared__ double s_acc;
    if (threadIdx.x == 0) s_acc = 0.0;
    __syncthreads();

    const int i0 = blockIdx.x * blockDim.x + threadIdx.x;   // float8 index

    // loop-invariant geometry: e = i*8; row = (i>>5)&255; col0 = (i&31)*8
    const float rowf = (float)((i0 >> 5) & 255);
    const float j0   = (float)((i0 & 31) * 8);
    int f = i0 >> 13;                                        // 8192 float8/frame

    const int stride = LOSS_GRID * 256;

    float lsum0 = 0.f, lsum1 = 0.f;
    for (int i = i0; i < total8; i += stride, f += FRAME_STEP) {
        const float2 cc = __ldg(&g_c[f]);          // 2KB table, L1-resident

        const f8 p8 = ldg256(inp + (size_t)i * 8);
        const f8 t8 = ldg256(tgt + (size_t)i * 8);

        const float di  = rowf - cc.x;
        const float di2 = di * di;
        const float jb  = j0 - cc.y;               // dj for lane c = jb + c

        #pragma unroll
        for (int c = 0; c < 8; c++) {
            const float p = p8.v[c];
            const float t = t8.v[c];

            const float dj = jb + (float)c;
            const float s  = fmaf(dj, dj, di2);
            float dist, wrcp;
            asm("sqrt.approx.f32 %0, %1;" : "=f"(dist) : "f"(s));    // sqrt.approx(0)=0
            asm("rcp.approx.f32 %0, %1;"  : "=f"(wrcp) : "f"(dist + 1.0f));

            float lp2, lq2;
            asm("lg2.approx.f32 %0, %1;" : "=f"(lp2) : "f"(p));
            asm("lg2.approx.f32 %0, %1;" : "=f"(lq2) : "f"(1.0f - p));
            lp2 = fmaxf(lp2, LOG2_CLAMP);
            lq2 = fmaxf(lq2, LOG2_CLAMP);
            const float term = fmaf(t, lp2 - lq2, lq2);   // log2 domain
            if (c & 1) lsum1 = fmaf(256.0f * wrcp, term, lsum1);
            else       lsum0 = fmaf(256.0f * wrcp, term, lsum0);
        }
    }
    float lsum = (lsum0 + lsum1) * LN2F;

    #pragma unroll
    for (int o = 16; o; o >>= 1) lsum += __shfl_xor_sync(0xffffffffu, lsum, o);
    if ((threadIdx.x & 31) == 0) atomicAdd(&s_acc, (double)lsum);
    __syncthreads();

    if (threadIdx.x == 0) {
        atomicAdd(&g_acc, s_acc);
        __threadfence();
        const unsigned t = atomicAdd(&g_done, 1u);
        if (t == gridDim.x - 1) {
            const double total = atomicAdd(&g_acc, 0.0);
            out[0] = (float)(-total * inv_n);
        }
    }
}

extern "C" void kernel_launch(void* const* d_in, const int* in_sizes, int n_in,
                              void* d_out, int out_size)
{
    const float* inp = (const float*)d_in[0];
    const float* tgt = (const float*)d_in[1];
    float* out = (float*)d_out;

    const int n       = in_sizes[1];       // B*T*W*W
    const int nframes = n >> 16;
    const int total8  = n >> 3;

    frame_stats_kernel<<<nframes, 1024>>>(tgt);
    loss_kernel<<<LOSS_GRID, 256>>>(inp, tgt, total8, out, 1.0 / (double)n);
}